// round 8
// baseline (speedup 1.0000x reference)
#include <cuda_runtime.h>
#include <cstdint>

// Problem constants (fixed by the dataset)
#define MROWS 8192
#define NCOLS 8192
#define KROWS 8192
#define NNZ   256
#define BATCH 32

#define WARPS_PER_CTA 16
#define CTA_THREADS   (WARPS_PER_CTA * 32)

// Intermediate bx = B @ x, [KROWS, BATCH] row-major. 1 MB device-global scratch.
__device__ float g_bx[KROWS * BATCH];

// Pure quad-line mode (R4 structure — best measured config; R5 proved the LSU
// front-end is a single shared pipe, so mode-mixing cannot help):
//   - warp = one output row; 4 subgroups of 8 lanes
//   - g = lane>>3 : nnz subgroup,  c = lane&7 : batch quad (4 floats)
//   - each LDG.128 gathers 4 distinct fully-used 128B lines (4 nnz)
// This round's deltas vs R4:
//   - metadata via LDS.128 serving 8 nnz per wavefront (2 pairs/subgroup)
//   - 8 LDG.128s in flight per warp (unroll), 16 warps/CTA for pipe pressure
template<int OUT_TRANSPOSED>
__global__ void __launch_bounds__(CTA_THREADS)
ell_spmm_kernel(const int*   __restrict__ idx,
                const float* __restrict__ vals,
                const float* __restrict__ src,
                float*       __restrict__ dst)
{
    // Interleaved (idx, val_bits) pairs; 16B-aligned for LDS.128. 2KB/warp.
    __shared__ __align__(16) uint2 s_pair[WARPS_PER_CTA][NNZ];

    const int warp = threadIdx.x >> 5;
    const int lane = threadIdx.x & 31;
    const int g    = lane >> 3;        // nnz subgroup 0..3
    const int c    = lane & 7;         // batch quad 0..7
    const int row  = blockIdx.x * WARPS_PER_CTA + warp;

    // Stage metadata: coalesced int4/float4 global loads, interleaved smem writes.
    {
        const int4*   ip = reinterpret_cast<const int4*>(idx  + (size_t)row * NNZ);
        const float4* vp = reinterpret_cast<const float4*>(vals + (size_t)row * NNZ);
#pragma unroll
        for (int q = 0; q < NNZ / (32 * 4); ++q) {
            const int4   iv = ip[q * 32 + lane];
            const float4 vv = vp[q * 32 + lane];
            const int base = (q * 32 + lane) * 4;
            s_pair[warp][base + 0] = make_uint2((unsigned)iv.x, __float_as_uint(vv.x));
            s_pair[warp][base + 1] = make_uint2((unsigned)iv.y, __float_as_uint(vv.y));
            s_pair[warp][base + 2] = make_uint2((unsigned)iv.z, __float_as_uint(vv.z));
            s_pair[warp][base + 3] = make_uint2((unsigned)iv.w, __float_as_uint(vv.w));
        }
    }
    __syncwarp();

    const float4* src4 = reinterpret_cast<const float4*>(src) + c;  // lane's batch quad
    float4 acc0 = make_float4(0.f, 0.f, 0.f, 0.f);
    float4 acc1 = make_float4(0.f, 0.f, 0.f, 0.f);

    // Each iteration: 1 LDS.128 (metadata for 8 nnz across 4 subgroups)
    //               + 2 LDG.128 (8 gathered lines). Unroll 4 => 8 LDGs in flight.
    const uint4* sp = reinterpret_cast<const uint4*>(s_pair[warp]);
#pragma unroll 4
    for (int t = 0; t < NNZ / 8; ++t) {
        // Subgroup g owns nnz {8t+2g, 8t+2g+1}: one 16B read of 2 pairs.
        const uint4 p = sp[t * 4 + g];   // {idx0, val0, idx1, val1}
        const float4 d0 = __ldg(&src4[(size_t)p.x * (BATCH / 4)]);
        const float4 d1 = __ldg(&src4[(size_t)p.z * (BATCH / 4)]);
        const float v0 = __uint_as_float(p.y);
        const float v1 = __uint_as_float(p.w);
        acc0.x = fmaf(v0, d0.x, acc0.x);
        acc0.y = fmaf(v0, d0.y, acc0.y);
        acc0.z = fmaf(v0, d0.z, acc0.z);
        acc0.w = fmaf(v0, d0.w, acc0.w);
        acc1.x = fmaf(v1, d1.x, acc1.x);
        acc1.y = fmaf(v1, d1.y, acc1.y);
        acc1.z = fmaf(v1, d1.z, acc1.z);
        acc1.w = fmaf(v1, d1.w, acc1.w);
    }
    float4 acc;
    acc.x = acc0.x + acc1.x;
    acc.y = acc0.y + acc1.y;
    acc.z = acc0.z + acc1.z;
    acc.w = acc0.w + acc1.w;

    // Reduce over the 4 nnz subgroups (lanes 8 apart share batch quad c).
#pragma unroll
    for (int off = 8; off < 32; off <<= 1) {
        acc.x += __shfl_xor_sync(0xffffffffu, acc.x, off);
        acc.y += __shfl_xor_sync(0xffffffffu, acc.y, off);
        acc.z += __shfl_xor_sync(0xffffffffu, acc.z, off);
        acc.w += __shfl_xor_sync(0xffffffffu, acc.w, off);
    }

    if (g == 0) {  // lanes 0..7 hold the row result for batches 4c..4c+3
        if (OUT_TRANSPOSED) {
            dst[(size_t)(4 * c + 0) * MROWS + row] = acc.x;
            dst[(size_t)(4 * c + 1) * MROWS + row] = acc.y;
            dst[(size_t)(4 * c + 2) * MROWS + row] = acc.z;
            dst[(size_t)(4 * c + 3) * MROWS + row] = acc.w;
        } else {
            reinterpret_cast<float4*>(dst + (size_t)row * BATCH)[c] = acc;  // STG.128
        }
    }
}

extern "C" void kernel_launch(void* const* d_in, const int* in_sizes, int n_in,
                              void* d_out, int out_size)
{
    // metadata order:
    //   0: x      float32 [8192, 32]
    //   1: a_idx  int32   [8192, 256]
    //   2: a_vals float32 [8192, 256]
    //   3: b_idx  int32   [8192, 256]
    //   4: b_vals float32 [8192, 256]
    const float* x      = (const float*)d_in[0];
    const int*   a_idx  = (const int*)  d_in[1];
    const float* a_vals = (const float*)d_in[2];
    const int*   b_idx  = (const int*)  d_in[3];
    const float* b_vals = (const float*)d_in[4];
    float* out = (float*)d_out;  // (1, 32, 8192) fp32

    float* bx;
    cudaGetSymbolAddress((void**)&bx, g_bx);

    // Stage 1: bx = B @ x
    ell_spmm_kernel<0><<<KROWS / WARPS_PER_CTA, CTA_THREADS>>>(b_idx, b_vals, x, bx);
    // Stage 2: out = (A @ bx)^T
    ell_spmm_kernel<1><<<MROWS / WARPS_PER_CTA, CTA_THREADS>>>(a_idx, a_vals, bx, out);
}

// round 9
// speedup vs baseline: 1.3938x; 1.3938x over previous
#include <cuda_runtime.h>
#include <cuda_fp16.h>
#include <cstdint>

// Problem constants (fixed by the dataset)
#define MROWS 8192
#define NCOLS 8192
#define KROWS 8192
#define NNZ   256
#define BATCH 32

// Intermediate bx = B @ x stored as fp16, [KROWS, BATCH] row-major (512 KB).
// Halves stage-2 gather bytes (64B rows) and doubles its L1-resident fraction.
__device__ __half g_bx[KROWS * BATCH];

// ── Stage 1: fp32 gather of x, fp16 store of bx. Exactly R4's proven quad-line
//    structure: warp=row, 4 subgroups (g) x 8 lanes (c = batch quad).
__global__ void __launch_bounds__(256)
ell_stage1_kernel(const int*   __restrict__ idx,
                  const float* __restrict__ vals,
                  const float* __restrict__ src,
                  __half*      __restrict__ dst)
{
    __shared__ __align__(16) uint2 s_pair[8][NNZ];

    const int warp = threadIdx.x >> 5;
    const int lane = threadIdx.x & 31;
    const int g    = lane >> 3;
    const int c    = lane & 7;
    const int row  = blockIdx.x * 8 + warp;

    {
        const int4*   ip = reinterpret_cast<const int4*>(idx  + (size_t)row * NNZ);
        const float4* vp = reinterpret_cast<const float4*>(vals + (size_t)row * NNZ);
#pragma unroll
        for (int q = 0; q < NNZ / (32 * 4); ++q) {
            const int4   iv = ip[q * 32 + lane];
            const float4 vv = vp[q * 32 + lane];
            const int base = (q * 32 + lane) * 4;
            s_pair[warp][base + 0] = make_uint2((unsigned)iv.x, __float_as_uint(vv.x));
            s_pair[warp][base + 1] = make_uint2((unsigned)iv.y, __float_as_uint(vv.y));
            s_pair[warp][base + 2] = make_uint2((unsigned)iv.z, __float_as_uint(vv.z));
            s_pair[warp][base + 3] = make_uint2((unsigned)iv.w, __float_as_uint(vv.w));
        }
    }
    __syncwarp();

    const float4* src4 = reinterpret_cast<const float4*>(src) + c;
    float4 acc = make_float4(0.f, 0.f, 0.f, 0.f);

#pragma unroll 4
    for (int t = 0; t < NNZ / 4; ++t) {
        const uint2  p = s_pair[warp][t * 4 + g];       // LDS.64, 4-group broadcast
        const float4 d = __ldg(&src4[(size_t)p.x * (BATCH / 4)]);  // 4 lines / instr
        const float  v = __uint_as_float(p.y);
        acc.x = fmaf(v, d.x, acc.x);
        acc.y = fmaf(v, d.y, acc.y);
        acc.z = fmaf(v, d.z, acc.z);
        acc.w = fmaf(v, d.w, acc.w);
    }

#pragma unroll
    for (int off = 8; off < 32; off <<= 1) {
        acc.x += __shfl_xor_sync(0xffffffffu, acc.x, off);
        acc.y += __shfl_xor_sync(0xffffffffu, acc.y, off);
        acc.z += __shfl_xor_sync(0xffffffffu, acc.z, off);
        acc.w += __shfl_xor_sync(0xffffffffu, acc.w, off);
    }

    if (g == 0) {  // lanes 0..7: write 4 fp16 batches each => one 64B STG.64 row
        const __half2 h0 = __floats2half2_rn(acc.x, acc.y);
        const __half2 h1 = __floats2half2_rn(acc.z, acc.w);
        uint2 s;
        s.x = *reinterpret_cast<const unsigned*>(&h0);
        s.y = *reinterpret_cast<const unsigned*>(&h1);
        reinterpret_cast<uint2*>(dst + (size_t)row * BATCH)[c] = s;
    }
}

// ── Stage 2: fp16 gather of bx (64B rows, LDG.64 quad mode), fp32 accumulate,
//    transposed fp32 output. Same subgroup geometry as stage 1.
__global__ void __launch_bounds__(256)
ell_stage2_kernel(const int*    __restrict__ idx,
                  const float*  __restrict__ vals,
                  const __half* __restrict__ src,
                  float*        __restrict__ dst)
{
    __shared__ __align__(16) uint2 s_pair[8][NNZ];

    const int warp = threadIdx.x >> 5;
    const int lane = threadIdx.x & 31;
    const int g    = lane >> 3;
    const int c    = lane & 7;
    const int row  = blockIdx.x * 8 + warp;

    {
        const int4*   ip = reinterpret_cast<const int4*>(idx  + (size_t)row * NNZ);
        const float4* vp = reinterpret_cast<const float4*>(vals + (size_t)row * NNZ);
#pragma unroll
        for (int q = 0; q < NNZ / (32 * 4); ++q) {
            const int4   iv = ip[q * 32 + lane];
            const float4 vv = vp[q * 32 + lane];
            const int base = (q * 32 + lane) * 4;
            s_pair[warp][base + 0] = make_uint2((unsigned)iv.x, __float_as_uint(vv.x));
            s_pair[warp][base + 1] = make_uint2((unsigned)iv.y, __float_as_uint(vv.y));
            s_pair[warp][base + 2] = make_uint2((unsigned)iv.z, __float_as_uint(vv.z));
            s_pair[warp][base + 3] = make_uint2((unsigned)iv.w, __float_as_uint(vv.w));
        }
    }
    __syncwarp();

    // Lane's 8B slice (4 fp16 = batches 4c..4c+3) of each 64B bx row.
    const uint2* src2 = reinterpret_cast<const uint2*>(src) + c;
    float4 acc = make_float4(0.f, 0.f, 0.f, 0.f);

#pragma unroll 4
    for (int t = 0; t < NNZ / 4; ++t) {
        const uint2 p = s_pair[warp][t * 4 + g];          // LDS.64 metadata
        const uint2 d = __ldg(&src2[(size_t)p.x * (BATCH / 4)]);  // LDG.64: 4 lines/instr
        const float v = __uint_as_float(p.y);
        const float2 f0 = __half22float2(*reinterpret_cast<const __half2*>(&d.x));
        const float2 f1 = __half22float2(*reinterpret_cast<const __half2*>(&d.y));
        acc.x = fmaf(v, f0.x, acc.x);
        acc.y = fmaf(v, f0.y, acc.y);
        acc.z = fmaf(v, f1.x, acc.z);
        acc.w = fmaf(v, f1.y, acc.w);
    }

#pragma unroll
    for (int off = 8; off < 32; off <<= 1) {
        acc.x += __shfl_xor_sync(0xffffffffu, acc.x, off);
        acc.y += __shfl_xor_sync(0xffffffffu, acc.y, off);
        acc.z += __shfl_xor_sync(0xffffffffu, acc.z, off);
        acc.w += __shfl_xor_sync(0xffffffffu, acc.w, off);
    }

    if (g == 0) {  // out[b][m], b = 4c..4c+3
        dst[(size_t)(4 * c + 0) * MROWS + row] = acc.x;
        dst[(size_t)(4 * c + 1) * MROWS + row] = acc.y;
        dst[(size_t)(4 * c + 2) * MROWS + row] = acc.z;
        dst[(size_t)(4 * c + 3) * MROWS + row] = acc.w;
    }
}

extern "C" void kernel_launch(void* const* d_in, const int* in_sizes, int n_in,
                              void* d_out, int out_size)
{
    // metadata order:
    //   0: x      float32 [8192, 32]
    //   1: a_idx  int32   [8192, 256]
    //   2: a_vals float32 [8192, 256]
    //   3: b_idx  int32   [8192, 256]
    //   4: b_vals float32 [8192, 256]
    const float* x      = (const float*)d_in[0];
    const int*   a_idx  = (const int*)  d_in[1];
    const float* a_vals = (const float*)d_in[2];
    const int*   b_idx  = (const int*)  d_in[3];
    const float* b_vals = (const float*)d_in[4];
    float* out = (float*)d_out;  // (1, 32, 8192) fp32

    __half* bx;
    cudaGetSymbolAddress((void**)&bx, g_bx);

    // Stage 1: bx = fp16(B @ x)   (fp32 gathers of x, fp32 accumulation)
    ell_stage1_kernel<<<KROWS / 8, 256>>>(b_idx, b_vals, x, bx);
    // Stage 2: out = (A @ bx)^T   (fp16 gathers, fp32 accumulation)
    ell_stage2_kernel<<<MROWS / 8, 256>>>(a_idx, a_vals, bx, out);
}